// round 1
// baseline (speedup 1.0000x reference)
#include <cuda_runtime.h>
#include <math.h>

// Problem constants (from reference setup_inputs)
#define NN 50000
#define EE 800000
#define DD 128
#define HH 128
#define BN_EPS 1e-3f

// ---------------- device scratch (no allocation allowed) ----------------
__device__ float g_Wp0[128 * 128];
__device__ float g_bp0[128];
__device__ float g_Wp1[128 * 128];
__device__ float g_bp1[128];
__device__ float g_Wu0[256 * 128];
__device__ float g_bu0[128];
__device__ float g_Wu1[128 * 128];
__device__ float g_bu1[128];

__device__ float g_bufA[NN * 128];   // t0 of prep FFN, later u0 of update FFN
__device__ float g_prep[NN * 128];   // prep FFN output (per-node messages)
__device__ float g_agg[NN * 128];    // aggregated sums
__device__ float g_cnt[NN];          // per-node edge counts (float)

// ---------------- helpers ----------------
__device__ __forceinline__ float gelu_f(float x) {
    return 0.5f * x * (1.0f + erff(x * 0.70710678118654752f));
}

// ---------------- BN-fold kernels (run every launch; tiny) ----------------
// W'[i][j] = s_i * W[i][j],  s_i = g_i * rsqrt(v_i + eps)
__global__ void fold_w(const float* __restrict__ g, const float* __restrict__ v,
                       const float* __restrict__ W, float* __restrict__ Wout, int K) {
    int i = blockIdx.x * 256 + threadIdx.x;
    if (i >= K * 128) return;
    int r = i >> 7;
    float s = g[r] * rsqrtf(v[r] + BN_EPS);
    Wout[i] = W[i] * s;
}

// b'[j] = bias[j] + sum_i (b_i - m_i*s_i) * W[i][j]
__global__ void fold_b(const float* __restrict__ g, const float* __restrict__ b,
                       const float* __restrict__ m, const float* __restrict__ v,
                       const float* __restrict__ W, const float* __restrict__ bias,
                       float* __restrict__ bout, int K) {
    int j = threadIdx.x;  // 128 threads
    float acc = bias[j];
    for (int i = 0; i < K; i++) {
        float s = g[i] * rsqrtf(v[i] + BN_EPS);
        float t = b[i] - m[i] * s;
        acc = fmaf(t, W[i * 128 + j], acc);
    }
    bout[j] = acc;
}

// ---------------- zero agg + cnt ----------------
__global__ void zero_kernel() {
    int i = blockIdx.x * 256 + threadIdx.x;
    float4 z = make_float4(0.f, 0.f, 0.f, 0.f);
    if (i < NN * 128 / 4) reinterpret_cast<float4*>(g_agg)[i] = z;
    if (i < NN / 4)       reinterpret_cast<float4*>(g_cnt)[i] = z;
}

// ---------------- fused GEMM + bias + gelu,  Y[nrows,128] = gelu(X[nrows,K] @ W' + b') --------
// Block: 256 threads, 64 rows x 128 cols per block. Thread tile: 4 rows x 8 cols.
template <int K>
__global__ void __launch_bounds__(256, 2)
gemm_bias_gelu(const float* __restrict__ X, const float* __restrict__ W,
               const float* __restrict__ B, float* __restrict__ Y, int nrows) {
    constexpr int LDX = K + 4;
    extern __shared__ float sm[];
    float* ws = sm;               // K*128
    float* xs = sm + K * 128;     // 64*LDX

    const int tid = threadIdx.x;

    // stage W'
    {
        const float4* Wg = reinterpret_cast<const float4*>(W);
        float4* Ws4 = reinterpret_cast<float4*>(ws);
        #pragma unroll
        for (int i = tid; i < K * 32; i += 256) Ws4[i] = Wg[i];
    }
    // stage x tile
    const int row0 = blockIdx.x * 64;
    {
        constexpr int QK = K / 4;
        for (int idx = tid; idx < 64 * QK; idx += 256) {
            int r = idx / QK, k4 = idx % QK;
            int row = row0 + r;
            float4 val = make_float4(0.f, 0.f, 0.f, 0.f);
            if (row < nrows)
                val = reinterpret_cast<const float4*>(X + (size_t)row * K)[k4];
            *reinterpret_cast<float4*>(xs + r * LDX + k4 * 4) = val;
        }
    }
    __syncthreads();

    const int cg = tid & 15, rg = tid >> 4;
    const int c0 = cg * 8, r0 = rg * 4;

    float acc[4][8];
    #pragma unroll
    for (int i = 0; i < 4; i++)
        #pragma unroll
        for (int j = 0; j < 8; j++) acc[i][j] = 0.f;

    #pragma unroll 2
    for (int k = 0; k < K; k += 4) {
        float xv[4][4];
        #pragma unroll
        for (int i = 0; i < 4; i++) {
            float4 t = *reinterpret_cast<const float4*>(xs + (r0 + i) * LDX + k);
            xv[i][0] = t.x; xv[i][1] = t.y; xv[i][2] = t.z; xv[i][3] = t.w;
        }
        #pragma unroll
        for (int kk = 0; kk < 4; kk++) {
            float4 wA = *reinterpret_cast<const float4*>(ws + (k + kk) * 128 + c0);
            float4 wB = *reinterpret_cast<const float4*>(ws + (k + kk) * 128 + c0 + 4);
            float w8[8] = {wA.x, wA.y, wA.z, wA.w, wB.x, wB.y, wB.z, wB.w};
            #pragma unroll
            for (int i = 0; i < 4; i++)
                #pragma unroll
                for (int j = 0; j < 8; j++)
                    acc[i][j] = fmaf(xv[i][kk], w8[j], acc[i][j]);
        }
    }

    // epilogue: bias + gelu
    float4 bA = *reinterpret_cast<const float4*>(B + c0);
    float4 bB = *reinterpret_cast<const float4*>(B + c0 + 4);
    float bb[8] = {bA.x, bA.y, bA.z, bA.w, bB.x, bB.y, bB.z, bB.w};
    #pragma unroll
    for (int i = 0; i < 4; i++) {
        int row = row0 + r0 + i;
        if (row < nrows) {
            float o[8];
            #pragma unroll
            for (int j = 0; j < 8; j++) o[j] = gelu_f(acc[i][j] + bb[j]);
            *reinterpret_cast<float4*>(Y + (size_t)row * 128 + c0) =
                make_float4(o[0], o[1], o[2], o[3]);
            *reinterpret_cast<float4*>(Y + (size_t)row * 128 + c0 + 4) =
                make_float4(o[4], o[5], o[6], o[7]);
        }
    }
}

// ---------------- update layer 0: x = [node_repr | agg_mean], K=256 ----------------
__global__ void __launch_bounds__(256, 1)
gemm_upd0(const float* __restrict__ Xa, const float* __restrict__ B,
          float* __restrict__ Y, int nrows) {
    constexpr int K = 256;
    constexpr int LDX = K + 4;
    extern __shared__ float sm[];
    float* ws = sm;
    float* xs = sm + K * 128;

    const int tid = threadIdx.x;
    {
        const float4* Wg = reinterpret_cast<const float4*>(g_Wu0);
        float4* Ws4 = reinterpret_cast<float4*>(ws);
        #pragma unroll
        for (int i = tid; i < K * 32; i += 256) Ws4[i] = Wg[i];
    }
    const int row0 = blockIdx.x * 64;
    {
        constexpr int QK = K / 4;  // 64 float4 per row
        for (int idx = tid; idx < 64 * QK; idx += 256) {
            int r = idx / QK, k4 = idx % QK;
            int row = row0 + r;
            float4 val = make_float4(0.f, 0.f, 0.f, 0.f);
            if (row < nrows) {
                if (k4 < 32) {
                    val = reinterpret_cast<const float4*>(Xa + (size_t)row * 128)[k4];
                } else {
                    float c = g_cnt[row];
                    float f = (c > 0.f) ? (1.0f / c) : 0.f;
                    val = reinterpret_cast<const float4*>(g_agg + (size_t)row * 128)[k4 - 32];
                    val.x *= f; val.y *= f; val.z *= f; val.w *= f;
                }
            }
            *reinterpret_cast<float4*>(xs + r * LDX + k4 * 4) = val;
        }
    }
    __syncthreads();

    const int cg = tid & 15, rg = tid >> 4;
    const int c0 = cg * 8, r0 = rg * 4;

    float acc[4][8];
    #pragma unroll
    for (int i = 0; i < 4; i++)
        #pragma unroll
        for (int j = 0; j < 8; j++) acc[i][j] = 0.f;

    #pragma unroll 2
    for (int k = 0; k < K; k += 4) {
        float xv[4][4];
        #pragma unroll
        for (int i = 0; i < 4; i++) {
            float4 t = *reinterpret_cast<const float4*>(xs + (r0 + i) * LDX + k);
            xv[i][0] = t.x; xv[i][1] = t.y; xv[i][2] = t.z; xv[i][3] = t.w;
        }
        #pragma unroll
        for (int kk = 0; kk < 4; kk++) {
            float4 wA = *reinterpret_cast<const float4*>(ws + (k + kk) * 128 + c0);
            float4 wB = *reinterpret_cast<const float4*>(ws + (k + kk) * 128 + c0 + 4);
            float w8[8] = {wA.x, wA.y, wA.z, wA.w, wB.x, wB.y, wB.z, wB.w};
            #pragma unroll
            for (int i = 0; i < 4; i++)
                #pragma unroll
                for (int j = 0; j < 8; j++)
                    acc[i][j] = fmaf(xv[i][kk], w8[j], acc[i][j]);
        }
    }

    float4 bA = *reinterpret_cast<const float4*>(B + c0);
    float4 bB = *reinterpret_cast<const float4*>(B + c0 + 4);
    float bb[8] = {bA.x, bA.y, bA.z, bA.w, bB.x, bB.y, bB.z, bB.w};
    #pragma unroll
    for (int i = 0; i < 4; i++) {
        int row = row0 + r0 + i;
        if (row < nrows) {
            float o[8];
            #pragma unroll
            for (int j = 0; j < 8; j++) o[j] = gelu_f(acc[i][j] + bb[j]);
            *reinterpret_cast<float4*>(Y + (size_t)row * 128 + c0) =
                make_float4(o[0], o[1], o[2], o[3]);
            *reinterpret_cast<float4*>(Y + (size_t)row * 128 + c0 + 4) =
                make_float4(o[4], o[5], o[6], o[7]);
        }
    }
}

// ---------------- edge scatter: one warp per edge ----------------
// agg[dst] += prep[src] * w ;  cnt[dst] += 1
__global__ void __launch_bounds__(256)
scatter_kernel(const int* __restrict__ edges, const float* __restrict__ ew) {
    int e = blockIdx.x * 8 + (threadIdx.x >> 5);
    if (e >= EE) return;
    int lane = threadIdx.x & 31;
    int dst = edges[e];        // node_indices
    int src = edges[EE + e];   // neighbour_indices
    float w = ew[e];

    float4 v = reinterpret_cast<const float4*>(g_prep + (size_t)src * 128)[lane];
    v.x *= w; v.y *= w; v.z *= w; v.w *= w;
    float* dp = g_agg + (size_t)dst * 128 + lane * 4;
    asm volatile("red.global.add.v4.f32 [%0], {%1, %2, %3, %4};"
                 :: "l"(dp), "f"(v.x), "f"(v.y), "f"(v.z), "f"(v.w)
                 : "memory");
    if (lane == 0) {
        asm volatile("red.global.add.f32 [%0], %1;"
                     :: "l"(g_cnt + dst), "f"(1.0f)
                     : "memory");
    }
}

// ---------------- launch ----------------
extern "C" void kernel_launch(void* const* d_in, const int* in_sizes, int n_in,
                              void* d_out, int out_size) {
    const float* node_repr = (const float*)d_in[0];
    const int*   edges     = (const int*)d_in[1];
    const float* edge_w    = (const float*)d_in[2];

    // prep layer 0: idx 3..8, prep layer 1: 9..14, upd layer 0: 15..20, upd layer 1: 21..26
    const float* p0g = (const float*)d_in[3];
    const float* p0b = (const float*)d_in[4];
    const float* p0m = (const float*)d_in[5];
    const float* p0v = (const float*)d_in[6];
    const float* p0W = (const float*)d_in[7];
    const float* p0bias = (const float*)d_in[8];
    const float* p1g = (const float*)d_in[9];
    const float* p1b = (const float*)d_in[10];
    const float* p1m = (const float*)d_in[11];
    const float* p1v = (const float*)d_in[12];
    const float* p1W = (const float*)d_in[13];
    const float* p1bias = (const float*)d_in[14];
    const float* u0g = (const float*)d_in[15];
    const float* u0b = (const float*)d_in[16];
    const float* u0m = (const float*)d_in[17];
    const float* u0v = (const float*)d_in[18];
    const float* u0W = (const float*)d_in[19];
    const float* u0bias = (const float*)d_in[20];
    const float* u1g = (const float*)d_in[21];
    const float* u1b = (const float*)d_in[22];
    const float* u1m = (const float*)d_in[23];
    const float* u1v = (const float*)d_in[24];
    const float* u1W = (const float*)d_in[25];
    const float* u1bias = (const float*)d_in[26];

    float *pWp0, *pbp0, *pWp1, *pbp1, *pWu0, *pbu0, *pWu1, *pbu1;
    float *pBufA, *pPrep;
    cudaGetSymbolAddress((void**)&pWp0, g_Wp0);
    cudaGetSymbolAddress((void**)&pbp0, g_bp0);
    cudaGetSymbolAddress((void**)&pWp1, g_Wp1);
    cudaGetSymbolAddress((void**)&pbp1, g_bp1);
    cudaGetSymbolAddress((void**)&pWu0, g_Wu0);
    cudaGetSymbolAddress((void**)&pbu0, g_bu0);
    cudaGetSymbolAddress((void**)&pWu1, g_Wu1);
    cudaGetSymbolAddress((void**)&pbu1, g_bu1);
    cudaGetSymbolAddress((void**)&pBufA, g_bufA);
    cudaGetSymbolAddress((void**)&pPrep, g_prep);

    const int smem128 = (128 * 128 + 64 * (128 + 4)) * 4;   // 99328 B
    const int smem256 = (256 * 128 + 64 * (256 + 4)) * 4;   // 197632 B
    cudaFuncSetAttribute(gemm_bias_gelu<128>, cudaFuncAttributeMaxDynamicSharedMemorySize, smem128);
    cudaFuncSetAttribute(gemm_upd0, cudaFuncAttributeMaxDynamicSharedMemorySize, smem256);

    // 1) fold BN into weights/biases
    fold_w<<<64, 256>>>(p0g, p0v, p0W, pWp0, 128);
    fold_w<<<64, 256>>>(p1g, p1v, p1W, pWp1, 128);
    fold_w<<<128, 256>>>(u0g, u0v, u0W, pWu0, 256);
    fold_w<<<64, 256>>>(u1g, u1v, u1W, pWu1, 128);
    fold_b<<<1, 128>>>(p0g, p0b, p0m, p0v, p0W, p0bias, pbp0, 128);
    fold_b<<<1, 128>>>(p1g, p1b, p1m, p1v, p1W, p1bias, pbp1, 128);
    fold_b<<<1, 128>>>(u0g, u0b, u0m, u0v, u0W, u0bias, pbu0, 256);
    fold_b<<<1, 128>>>(u1g, u1b, u1m, u1v, u1W, u1bias, pbu1, 128);

    // 2) zero aggregation buffers
    zero_kernel<<<(NN * 128 / 4 + 255) / 256, 256>>>();

    const int gblocks = (NN + 63) / 64;
    // 3) prepare FFN applied once per NODE (algebraic 16x reduction vs per-edge)
    gemm_bias_gelu<128><<<gblocks, 256, smem128>>>(node_repr, pWp0, pbp0, pBufA, NN);
    gemm_bias_gelu<128><<<gblocks, 256, smem128>>>(pBufA, pWp1, pbp1, pPrep, NN);

    // 4) scatter-aggregate along edges
    scatter_kernel<<<EE / 8, 256>>>(edges, edge_w);

    // 5) update FFN: concat(node_repr, agg_mean) -> H, then H -> H (writes d_out)
    gemm_upd0<<<gblocks, 256, smem256>>>(node_repr, pbu0, pBufA, NN);
    gemm_bias_gelu<128><<<gblocks, 256, smem128>>>(pBufA, pWu1, pbu1, (float*)d_out, NN);
}

// round 2
// speedup vs baseline: 1.6476x; 1.6476x over previous
#include <cuda_runtime.h>
#include <math.h>

#define NN 50000
#define EE 800000
#define BN_EPS 1e-3f

typedef unsigned long long ull;

// ---------------- device scratch (no allocation allowed) ----------------
__device__ float g_Wp0[128 * 128];
__device__ float g_bp0[128];
__device__ float g_Wp1[128 * 128];
__device__ float g_bp1[128];
__device__ float g_Wu0[256 * 128];
__device__ float g_bu0[128];
__device__ float g_Wu1[128 * 128];
__device__ float g_bu1[128];

__device__ float g_bufA[NN * 128];   // intermediate activations
__device__ float g_prep[NN * 128];   // prep FFN output (per-node messages)
__device__ float g_agg[NN * 128];    // aggregated sums
__device__ float g_cnt[NN];          // per-node edge counts

// ---------------- helpers ----------------
__device__ __forceinline__ ull ffma2(ull a, ull b, ull c) {
    ull d;
    asm("fma.rn.f32x2 %0, %1, %2, %3;" : "=l"(d) : "l"(a), "l"(b), "l"(c));
    return d;
}
__device__ __forceinline__ ull pack2(float x) {
    ull r;
    asm("mov.b64 %0, {%1, %2};" : "=l"(r) : "f"(x), "f"(x));
    return r;
}
__device__ __forceinline__ void unpack2(ull v, float& lo, float& hi) {
    asm("mov.b64 {%0, %1}, %2;" : "=f"(lo), "=f"(hi) : "l"(v));
}
__device__ __forceinline__ float gelu_f(float x) {
    return 0.5f * x * (1.0f + erff(x * 0.70710678118654752f));
}

// ---------------- fused BN-fold kernels (2 launches total) ----------------
// W'[i][j] = s_i * W[i][j],  s_i = g_i * rsqrt(v_i + eps)
__global__ void fold_w_all(
    const float* __restrict__ g0, const float* __restrict__ v0, const float* __restrict__ W0, float* __restrict__ o0,
    const float* __restrict__ g1, const float* __restrict__ v1, const float* __restrict__ W1, float* __restrict__ o1,
    const float* __restrict__ g2, const float* __restrict__ v2, const float* __restrict__ W2, float* __restrict__ o2,
    const float* __restrict__ g3, const float* __restrict__ v3, const float* __restrict__ W3, float* __restrict__ o3) {
    int idx = blockIdx.x * 256 + threadIdx.x;
    const float *g, *v, *W;
    float* o;
    int base;
    if (idx < 16384)      { g = g0; v = v0; W = W0; o = o0; base = 0; }
    else if (idx < 32768) { g = g1; v = v1; W = W1; o = o1; base = 16384; }
    else if (idx < 65536) { g = g2; v = v2; W = W2; o = o2; base = 32768; }
    else                  { g = g3; v = v3; W = W3; o = o3; base = 65536; if (idx >= 81920) return; }
    int i = idx - base;
    int r = i >> 7;
    o[i] = W[i] * (g[r] * rsqrtf(v[r] + BN_EPS));
}

// b'[j] = bias[j] + sum_i (b_i - m_i*s_i) * W[i][j]
__global__ void fold_b_all(
    const float* __restrict__ g0, const float* __restrict__ b0, const float* __restrict__ m0, const float* __restrict__ v0, const float* __restrict__ W0, const float* __restrict__ s0, float* __restrict__ o0,
    const float* __restrict__ g1, const float* __restrict__ b1, const float* __restrict__ m1, const float* __restrict__ v1, const float* __restrict__ W1, const float* __restrict__ s1, float* __restrict__ o1,
    const float* __restrict__ g2, const float* __restrict__ b2, const float* __restrict__ m2, const float* __restrict__ v2, const float* __restrict__ W2, const float* __restrict__ s2, float* __restrict__ o2,
    const float* __restrict__ g3, const float* __restrict__ b3, const float* __restrict__ m3, const float* __restrict__ v3, const float* __restrict__ W3, const float* __restrict__ s3, float* __restrict__ o3) {
    int l = blockIdx.x;
    const float *g, *b, *m, *v, *W, *s;
    float* o;
    int K;
    switch (l) {
        case 0:  g = g0; b = b0; m = m0; v = v0; W = W0; s = s0; o = o0; K = 128; break;
        case 1:  g = g1; b = b1; m = m1; v = v1; W = W1; s = s1; o = o1; K = 128; break;
        case 2:  g = g2; b = b2; m = m2; v = v2; W = W2; s = s2; o = o2; K = 256; break;
        default: g = g3; b = b3; m = m3; v = v3; W = W3; s = s3; o = o3; K = 128; break;
    }
    int j = threadIdx.x;
    float acc0 = s[j], acc1 = 0.f;
    #pragma unroll 8
    for (int i = 0; i < K; i += 2) {
        float sc0 = g[i] * rsqrtf(v[i] + BN_EPS);
        float sc1 = g[i + 1] * rsqrtf(v[i + 1] + BN_EPS);
        acc0 = fmaf(b[i] - m[i] * sc0, W[i * 128 + j], acc0);
        acc1 = fmaf(b[i + 1] - m[i + 1] * sc1, W[(i + 1) * 128 + j], acc1);
    }
    o[j] = acc0 + acc1;
}

// ---------------- zero agg + cnt ----------------
__global__ void zero_kernel() {
    int i = blockIdx.x * 256 + threadIdx.x;
    float4 z = make_float4(0.f, 0.f, 0.f, 0.f);
    if (i < NN * 128 / 4) reinterpret_cast<float4*>(g_agg)[i] = z;
    if (i < NN / 4)       reinterpret_cast<float4*>(g_cnt)[i] = z;
}

// ---------------- GEMM + bias + gelu with packed f32x2 FMA ----------------
// Y[nrows,128] = gelu(X[nrows, CHUNKS*128] @ W' + b')
// 128 threads, 64-row x 128-col block tile, 8x8 thread tile (as 8x4 f32x2 pairs).
// K processed in 128-wide chunks; each chunk stages W-chunk (64KB) + X-chunk into smem.
// CONCAT: chunk 0 reads X0 (node_repr), chunk 1 reads g_agg scaled by 1/cnt.
template <int CHUNKS, bool CONCAT>
__global__ void __launch_bounds__(128, 2)
gemm_f2(const float* __restrict__ X0, const float* __restrict__ W,
        const float* __restrict__ B, float* __restrict__ Y, int nrows) {
    constexpr int LDX = 132;             // floats per staged x row (132*4=528B, 16B-aligned)
    extern __shared__ float sm[];
    float* ws = sm;                      // 128*128 floats
    float* xs = sm + 128 * 128;          // 64*LDX floats

    const int tid = threadIdx.x;
    const int row0 = blockIdx.x * 64;

    ull acc[8][4];
    #pragma unroll
    for (int i = 0; i < 8; i++)
        #pragma unroll
        for (int j = 0; j < 4; j++) acc[i][j] = 0ull;

    const int cg = tid & 15, rg = tid >> 4;
    const int c0 = cg * 8;
    const int rloc = rg * 8;

    for (int cc = 0; cc < CHUNKS; cc++) {
        if (cc) __syncthreads();
        // stage W chunk (rows cc*128 .. cc*128+127)
        {
            const float4* Wg = reinterpret_cast<const float4*>(W + cc * 128 * 128);
            float4* Ws4 = reinterpret_cast<float4*>(ws);
            #pragma unroll
            for (int i = tid; i < 128 * 32; i += 128) Ws4[i] = Wg[i];
        }
        // stage X chunk
        {
            const float* Xc = (CONCAT && cc == 1) ? g_agg : X0;
            #pragma unroll
            for (int idx = tid; idx < 64 * 32; idx += 128) {
                int r = idx >> 5, k4 = idx & 31;
                int row = row0 + r;
                float4 v = make_float4(0.f, 0.f, 0.f, 0.f);
                if (row < nrows) {
                    v = reinterpret_cast<const float4*>(Xc + (size_t)row * 128)[k4];
                    if (CONCAT && cc == 1) {
                        float cn = g_cnt[row];
                        float f = (cn > 0.f) ? (1.0f / cn) : 0.f;
                        v.x *= f; v.y *= f; v.z *= f; v.w *= f;
                    }
                }
                *reinterpret_cast<float4*>(xs + r * LDX + k4 * 4) = v;
            }
        }
        __syncthreads();

        #pragma unroll 2
        for (int k = 0; k < 128; k += 4) {
            float4 xv[8];
            #pragma unroll
            for (int i = 0; i < 8; i++)
                xv[i] = *reinterpret_cast<const float4*>(xs + (rloc + i) * LDX + k);
            #pragma unroll
            for (int kk = 0; kk < 4; kk++) {
                ulonglong2 wa = *reinterpret_cast<const ulonglong2*>(ws + (k + kk) * 128 + c0);
                ulonglong2 wb = *reinterpret_cast<const ulonglong2*>(ws + (k + kk) * 128 + c0 + 4);
                #pragma unroll
                for (int i = 0; i < 8; i++) {
                    const float* xp = reinterpret_cast<const float*>(&xv[i]);
                    ull xd = pack2(xp[kk]);
                    acc[i][0] = ffma2(xd, wa.x, acc[i][0]);
                    acc[i][1] = ffma2(xd, wa.y, acc[i][1]);
                    acc[i][2] = ffma2(xd, wb.x, acc[i][2]);
                    acc[i][3] = ffma2(xd, wb.y, acc[i][3]);
                }
            }
        }
    }

    // epilogue: bias + gelu + store
    float4 bA = *reinterpret_cast<const float4*>(B + c0);
    float4 bB = *reinterpret_cast<const float4*>(B + c0 + 4);
    float bb[8] = {bA.x, bA.y, bA.z, bA.w, bB.x, bB.y, bB.z, bB.w};
    #pragma unroll
    for (int i = 0; i < 8; i++) {
        int row = row0 + rloc + i;
        if (row < nrows) {
            float o[8];
            #pragma unroll
            for (int j = 0; j < 4; j++) {
                float lo, hi;
                unpack2(acc[i][j], lo, hi);
                o[2 * j]     = gelu_f(lo + bb[2 * j]);
                o[2 * j + 1] = gelu_f(hi + bb[2 * j + 1]);
            }
            *reinterpret_cast<float4*>(Y + (size_t)row * 128 + c0) =
                make_float4(o[0], o[1], o[2], o[3]);
            *reinterpret_cast<float4*>(Y + (size_t)row * 128 + c0 + 4) =
                make_float4(o[4], o[5], o[6], o[7]);
        }
    }
}

// ---------------- edge scatter: one warp per 2 edges (doubled MLP) ----------------
// agg[dst] += prep[src] * w ;  cnt[dst] += 1
__global__ void __launch_bounds__(256)
scatter_kernel(const int* __restrict__ edges, const float* __restrict__ ew) {
    int warp = blockIdx.x * 8 + (threadIdx.x >> 5);
    int lane = threadIdx.x & 31;
    int e0 = warp * 2;

    int dst0 = __ldg(edges + e0);
    int dst1 = __ldg(edges + e0 + 1);
    int src0 = __ldg(edges + EE + e0);
    int src1 = __ldg(edges + EE + e0 + 1);
    float w0 = __ldg(ew + e0);
    float w1 = __ldg(ew + e0 + 1);

    float4 v0 = __ldg(reinterpret_cast<const float4*>(g_prep + (size_t)src0 * 128) + lane);
    float4 v1 = __ldg(reinterpret_cast<const float4*>(g_prep + (size_t)src1 * 128) + lane);
    v0.x *= w0; v0.y *= w0; v0.z *= w0; v0.w *= w0;
    v1.x *= w1; v1.y *= w1; v1.z *= w1; v1.w *= w1;

    float* dp0 = g_agg + (size_t)dst0 * 128 + lane * 4;
    float* dp1 = g_agg + (size_t)dst1 * 128 + lane * 4;
    asm volatile("red.global.add.v4.f32 [%0], {%1, %2, %3, %4};"
                 :: "l"(dp0), "f"(v0.x), "f"(v0.y), "f"(v0.z), "f"(v0.w) : "memory");
    asm volatile("red.global.add.v4.f32 [%0], {%1, %2, %3, %4};"
                 :: "l"(dp1), "f"(v1.x), "f"(v1.y), "f"(v1.z), "f"(v1.w) : "memory");
    if (lane == 0) {
        asm volatile("red.global.add.f32 [%0], %1;" :: "l"(g_cnt + dst0), "f"(1.0f) : "memory");
        asm volatile("red.global.add.f32 [%0], %1;" :: "l"(g_cnt + dst1), "f"(1.0f) : "memory");
    }
}

// ---------------- launch ----------------
extern "C" void kernel_launch(void* const* d_in, const int* in_sizes, int n_in,
                              void* d_out, int out_size) {
    const float* node_repr = (const float*)d_in[0];
    const int*   edges     = (const int*)d_in[1];
    const float* edge_w    = (const float*)d_in[2];

    const float* p0g = (const float*)d_in[3];  const float* p0b = (const float*)d_in[4];
    const float* p0m = (const float*)d_in[5];  const float* p0v = (const float*)d_in[6];
    const float* p0W = (const float*)d_in[7];  const float* p0bias = (const float*)d_in[8];
    const float* p1g = (const float*)d_in[9];  const float* p1b = (const float*)d_in[10];
    const float* p1m = (const float*)d_in[11]; const float* p1v = (const float*)d_in[12];
    const float* p1W = (const float*)d_in[13]; const float* p1bias = (const float*)d_in[14];
    const float* u0g = (const float*)d_in[15]; const float* u0b = (const float*)d_in[16];
    const float* u0m = (const float*)d_in[17]; const float* u0v = (const float*)d_in[18];
    const float* u0W = (const float*)d_in[19]; const float* u0bias = (const float*)d_in[20];
    const float* u1g = (const float*)d_in[21]; const float* u1b = (const float*)d_in[22];
    const float* u1m = (const float*)d_in[23]; const float* u1v = (const float*)d_in[24];
    const float* u1W = (const float*)d_in[25]; const float* u1bias = (const float*)d_in[26];

    float *pWp0, *pbp0, *pWp1, *pbp1, *pWu0, *pbu0, *pWu1, *pbu1, *pBufA, *pPrep;
    cudaGetSymbolAddress((void**)&pWp0, g_Wp0);
    cudaGetSymbolAddress((void**)&pbp0, g_bp0);
    cudaGetSymbolAddress((void**)&pWp1, g_Wp1);
    cudaGetSymbolAddress((void**)&pbp1, g_bp1);
    cudaGetSymbolAddress((void**)&pWu0, g_Wu0);
    cudaGetSymbolAddress((void**)&pbu0, g_bu0);
    cudaGetSymbolAddress((void**)&pWu1, g_Wu1);
    cudaGetSymbolAddress((void**)&pbu1, g_bu1);
    cudaGetSymbolAddress((void**)&pBufA, g_bufA);
    cudaGetSymbolAddress((void**)&pPrep, g_prep);

    const int smemB = (128 * 128 + 64 * 132) * 4;  // 99328 B
    cudaFuncSetAttribute(gemm_f2<1, false>, cudaFuncAttributeMaxDynamicSharedMemorySize, smemB);
    cudaFuncSetAttribute(gemm_f2<2, true>,  cudaFuncAttributeMaxDynamicSharedMemorySize, smemB);

    // 1) fold BN into weights/biases (2 launches)
    fold_w_all<<<320, 256>>>(p0g, p0v, p0W, pWp0,
                             p1g, p1v, p1W, pWp1,
                             u0g, u0v, u0W, pWu0,
                             u1g, u1v, u1W, pWu1);
    fold_b_all<<<4, 128>>>(p0g, p0b, p0m, p0v, p0W, p0bias, pbp0,
                           p1g, p1b, p1m, p1v, p1W, p1bias, pbp1,
                           u0g, u0b, u0m, u0v, u0W, u0bias, pbu0,
                           u1g, u1b, u1m, u1v, u1W, u1bias, pbu1);

    // 2) zero aggregation buffers
    zero_kernel<<<(NN * 128 / 4 + 255) / 256, 256>>>();

    const int gblocks = (NN + 63) / 64;  // 782
    // 3) prepare FFN applied once per NODE (16x algebraic reduction vs per-edge)
    gemm_f2<1, false><<<gblocks, 128, smemB>>>(node_repr, pWp0, pbp0, pBufA, NN);
    gemm_f2<1, false><<<gblocks, 128, smemB>>>(pBufA, pWp1, pbp1, pPrep, NN);

    // 4) scatter-aggregate along edges (2 edges per warp)
    scatter_kernel<<<EE / 16, 256>>>(edges, edge_w);

    // 5) update FFN: concat(node_repr, agg_mean) -> H, then H -> H (writes d_out)
    gemm_f2<2, true><<<gblocks, 128, smemB>>>(node_repr, pWu0, pbu0, pBufA, NN);
    gemm_f2<1, false><<<gblocks, 128, smemB>>>(pBufA, pWu1, pbu1, (float*)d_out, NN);
}

// round 3
// speedup vs baseline: 1.6520x; 1.0026x over previous
#include <cuda_runtime.h>
#include <math.h>

#define NN 50000
#define EE 800000
#define BN_EPS 1e-3f

typedef unsigned long long ull;

// ---------------- device scratch (no allocation allowed) ----------------
__device__ float g_Wp0[128 * 128];
__device__ float g_bp0[128];
__device__ float g_Wp1[128 * 128];
__device__ float g_bp1[128];
__device__ float g_Wu0[256 * 128];
__device__ float g_bu0[128];
__device__ float g_Wu1[128 * 128];
__device__ float g_bu1[128];

__device__ float g_bufA[NN * 128];   // intermediate activations
__device__ float g_prep[NN * 128];   // prep FFN output (per-node messages)
__device__ float g_agg[NN * 128];    // aggregated sums
__device__ float g_cnt[NN];          // per-node edge counts

// ---------------- helpers ----------------
__device__ __forceinline__ ull ffma2(ull a, ull b, ull c) {
    ull d;
    asm("fma.rn.f32x2 %0, %1, %2, %3;" : "=l"(d) : "l"(a), "l"(b), "l"(c));
    return d;
}
__device__ __forceinline__ ull pack2(float x) {
    ull r;
    asm("mov.b64 %0, {%1, %2};" : "=l"(r) : "f"(x), "f"(x));
    return r;
}
__device__ __forceinline__ void unpack2(ull v, float& lo, float& hi) {
    asm("mov.b64 {%0, %1}, %2;" : "=f"(lo), "=f"(hi) : "l"(v));
}
__device__ __forceinline__ float gelu_f(float x) {
    return 0.5f * x * (1.0f + erff(x * 0.70710678118654752f));
}

// ---------------- fused BN-fold kernels (2 launches total) ----------------
__global__ void fold_w_all(
    const float* __restrict__ g0, const float* __restrict__ v0, const float* __restrict__ W0, float* __restrict__ o0,
    const float* __restrict__ g1, const float* __restrict__ v1, const float* __restrict__ W1, float* __restrict__ o1,
    const float* __restrict__ g2, const float* __restrict__ v2, const float* __restrict__ W2, float* __restrict__ o2,
    const float* __restrict__ g3, const float* __restrict__ v3, const float* __restrict__ W3, float* __restrict__ o3) {
    int idx = blockIdx.x * 256 + threadIdx.x;
    const float *g, *v, *W;
    float* o;
    int base;
    if (idx < 16384)      { g = g0; v = v0; W = W0; o = o0; base = 0; }
    else if (idx < 32768) { g = g1; v = v1; W = W1; o = o1; base = 16384; }
    else if (idx < 65536) { g = g2; v = v2; W = W2; o = o2; base = 32768; }
    else                  { g = g3; v = v3; W = W3; o = o3; base = 65536; if (idx >= 81920) return; }
    int i = idx - base;
    int r = i >> 7;
    o[i] = W[i] * (g[r] * rsqrtf(v[r] + BN_EPS));
}

__global__ void fold_b_all(
    const float* __restrict__ g0, const float* __restrict__ b0, const float* __restrict__ m0, const float* __restrict__ v0, const float* __restrict__ W0, const float* __restrict__ s0, float* __restrict__ o0,
    const float* __restrict__ g1, const float* __restrict__ b1, const float* __restrict__ m1, const float* __restrict__ v1, const float* __restrict__ W1, const float* __restrict__ s1, float* __restrict__ o1,
    const float* __restrict__ g2, const float* __restrict__ b2, const float* __restrict__ m2, const float* __restrict__ v2, const float* __restrict__ W2, const float* __restrict__ s2, float* __restrict__ o2,
    const float* __restrict__ g3, const float* __restrict__ b3, const float* __restrict__ m3, const float* __restrict__ v3, const float* __restrict__ W3, const float* __restrict__ s3, float* __restrict__ o3) {
    int l = blockIdx.x;
    const float *g, *b, *m, *v, *W, *s;
    float* o;
    int K;
    switch (l) {
        case 0:  g = g0; b = b0; m = m0; v = v0; W = W0; s = s0; o = o0; K = 128; break;
        case 1:  g = g1; b = b1; m = m1; v = v1; W = W1; s = s1; o = o1; K = 128; break;
        case 2:  g = g2; b = b2; m = m2; v = v2; W = W2; s = s2; o = o2; K = 256; break;
        default: g = g3; b = b3; m = m3; v = v3; W = W3; s = s3; o = o3; K = 128; break;
    }
    int j = threadIdx.x;
    float acc0 = s[j], acc1 = 0.f;
    #pragma unroll 8
    for (int i = 0; i < K; i += 2) {
        float sc0 = g[i] * rsqrtf(v[i] + BN_EPS);
        float sc1 = g[i + 1] * rsqrtf(v[i + 1] + BN_EPS);
        acc0 = fmaf(b[i] - m[i] * sc0, W[i * 128 + j], acc0);
        acc1 = fmaf(b[i + 1] - m[i + 1] * sc1, W[(i + 1) * 128 + j], acc1);
    }
    o[j] = acc0 + acc1;
}

// ---------------- zero agg + cnt ----------------
__global__ void zero_kernel() {
    int i = blockIdx.x * 256 + threadIdx.x;
    float4 z = make_float4(0.f, 0.f, 0.f, 0.f);
    if (i < NN * 128 / 4) reinterpret_cast<float4*>(g_agg)[i] = z;
    if (i < NN / 4)       reinterpret_cast<float4*>(g_cnt)[i] = z;
}

// ---------------- GEMM + bias + gelu with packed f32x2 FMA ----------------
// Y[nrows,128] = gelu(X[nrows, CHUNKS*128] @ W' + b')
// 128 threads, block tile 64 rows x 128 cols.
// Warp = 32-col stripe; lane -> (rbase = lane>>2, c = lane&3).
// Thread tile: rows {rbase + 8*i, i=0..7} x cols {wid*32 + c*8 .. +8}.
//   W LDS.128: 4 distinct 16B lines, 64B contiguous -> 1 wavefront.
//   x LDS.128: 8 distinct lines at stride 528B (== 16 mod 128) -> conflict-free.
// x fragments register-double-buffered (prefetch next k-group during FMAs).
template <int CHUNKS, bool CONCAT>
__global__ void __launch_bounds__(128, 2)
gemm_f2(const float* __restrict__ X0, const float* __restrict__ W,
        const float* __restrict__ B, float* __restrict__ Y, int nrows) {
    constexpr int LDX = 132;             // 528B row stride in xs
    extern __shared__ float sm[];
    float* ws = sm;                      // 128*128 floats
    float* xs = sm + 128 * 128;          // 64*LDX floats

    const int tid = threadIdx.x;
    const int lane = tid & 31;
    const int wid = tid >> 5;
    const int c0 = wid * 32 + (lane & 3) * 8;
    const int rbase = lane >> 2;
    const int row0 = blockIdx.x * 64;

    ull acc[8][4];
    #pragma unroll
    for (int i = 0; i < 8; i++)
        #pragma unroll
        for (int j = 0; j < 4; j++) acc[i][j] = 0ull;

    for (int cc = 0; cc < CHUNKS; cc++) {
        if (cc) __syncthreads();
        // stage W chunk (k rows cc*128 .. +127), row-major [k][128]
        {
            const float4* Wg = reinterpret_cast<const float4*>(W + cc * 128 * 128);
            float4* Ws4 = reinterpret_cast<float4*>(ws);
            #pragma unroll
            for (int i = tid; i < 128 * 32; i += 128) Ws4[i] = Wg[i];
        }
        // stage X chunk
        {
            const float* Xc = (CONCAT && cc == 1) ? g_agg : X0;
            #pragma unroll
            for (int idx = tid; idx < 64 * 32; idx += 128) {
                int r = idx >> 5, k4 = idx & 31;
                int row = row0 + r;
                float4 v = make_float4(0.f, 0.f, 0.f, 0.f);
                if (row < nrows) {
                    v = reinterpret_cast<const float4*>(Xc + (size_t)row * 128)[k4];
                    if (CONCAT && cc == 1) {
                        float cn = g_cnt[row];
                        float f = (cn > 0.f) ? (1.0f / cn) : 0.f;
                        v.x *= f; v.y *= f; v.z *= f; v.w *= f;
                    }
                }
                *reinterpret_cast<float4*>(xs + r * LDX + k4 * 4) = v;
            }
        }
        __syncthreads();

        float4 xa[8], xb[8];
        #pragma unroll
        for (int i = 0; i < 8; i++)
            xa[i] = *reinterpret_cast<const float4*>(xs + (rbase + 8 * i) * LDX);

        #pragma unroll 1
        for (int kg = 0; kg < 32; kg += 2) {
            // prefetch group kg+1 into xb, compute group kg from xa
            #pragma unroll
            for (int i = 0; i < 8; i++)
                xb[i] = *reinterpret_cast<const float4*>(xs + (rbase + 8 * i) * LDX + kg * 4 + 4);
            #pragma unroll
            for (int kk = 0; kk < 4; kk++) {
                int k = kg * 4 + kk;
                ulonglong2 wa = *reinterpret_cast<const ulonglong2*>(ws + k * 128 + c0);
                ulonglong2 wb = *reinterpret_cast<const ulonglong2*>(ws + k * 128 + c0 + 4);
                #pragma unroll
                for (int i = 0; i < 8; i++) {
                    const float* xp = reinterpret_cast<const float*>(&xa[i]);
                    ull xd = pack2(xp[kk]);
                    acc[i][0] = ffma2(xd, wa.x, acc[i][0]);
                    acc[i][1] = ffma2(xd, wa.y, acc[i][1]);
                    acc[i][2] = ffma2(xd, wb.x, acc[i][2]);
                    acc[i][3] = ffma2(xd, wb.y, acc[i][3]);
                }
            }
            // prefetch group kg+2 into xa (if any), compute group kg+1 from xb
            if (kg < 30) {
                #pragma unroll
                for (int i = 0; i < 8; i++)
                    xa[i] = *reinterpret_cast<const float4*>(xs + (rbase + 8 * i) * LDX + kg * 4 + 8);
            }
            #pragma unroll
            for (int kk = 0; kk < 4; kk++) {
                int k = kg * 4 + 4 + kk;
                ulonglong2 wa = *reinterpret_cast<const ulonglong2*>(ws + k * 128 + c0);
                ulonglong2 wb = *reinterpret_cast<const ulonglong2*>(ws + k * 128 + c0 + 4);
                #pragma unroll
                for (int i = 0; i < 8; i++) {
                    const float* xp = reinterpret_cast<const float*>(&xb[i]);
                    ull xd = pack2(xp[kk]);
                    acc[i][0] = ffma2(xd, wa.x, acc[i][0]);
                    acc[i][1] = ffma2(xd, wa.y, acc[i][1]);
                    acc[i][2] = ffma2(xd, wb.x, acc[i][2]);
                    acc[i][3] = ffma2(xd, wb.y, acc[i][3]);
                }
            }
        }
    }

    // epilogue: bias + gelu + store (rows rbase + 8*i)
    float4 bA = *reinterpret_cast<const float4*>(B + c0);
    float4 bB = *reinterpret_cast<const float4*>(B + c0 + 4);
    float bb[8] = {bA.x, bA.y, bA.z, bA.w, bB.x, bB.y, bB.z, bB.w};
    #pragma unroll
    for (int i = 0; i < 8; i++) {
        int row = row0 + rbase + 8 * i;
        if (row < nrows) {
            float o[8];
            #pragma unroll
            for (int j = 0; j < 4; j++) {
                float lo, hi;
                unpack2(acc[i][j], lo, hi);
                o[2 * j]     = gelu_f(lo + bb[2 * j]);
                o[2 * j + 1] = gelu_f(hi + bb[2 * j + 1]);
            }
            *reinterpret_cast<float4*>(Y + (size_t)row * 128 + c0) =
                make_float4(o[0], o[1], o[2], o[3]);
            *reinterpret_cast<float4*>(Y + (size_t)row * 128 + c0 + 4) =
                make_float4(o[4], o[5], o[6], o[7]);
        }
    }
}

// ---------------- edge scatter: 4 edges per warp, loads batched for MLP ----------------
__global__ void __launch_bounds__(256)
scatter_kernel(const int* __restrict__ edges, const float* __restrict__ ew) {
    int warp = blockIdx.x * 8 + (threadIdx.x >> 5);
    int lane = threadIdx.x & 31;
    int e0 = warp * 4;

    int dst[4], src[4];
    float w[4];
    #pragma unroll
    for (int t = 0; t < 4; t++) {
        dst[t] = __ldg(edges + e0 + t);
        src[t] = __ldg(edges + EE + e0 + t);
        w[t]   = __ldg(ew + e0 + t);
    }
    float4 v[4];
    #pragma unroll
    for (int t = 0; t < 4; t++)
        v[t] = __ldg(reinterpret_cast<const float4*>(g_prep + (size_t)src[t] * 128) + lane);
    #pragma unroll
    for (int t = 0; t < 4; t++) {
        v[t].x *= w[t]; v[t].y *= w[t]; v[t].z *= w[t]; v[t].w *= w[t];
        float* dp = g_agg + (size_t)dst[t] * 128 + lane * 4;
        asm volatile("red.global.add.v4.f32 [%0], {%1, %2, %3, %4};"
                     :: "l"(dp), "f"(v[t].x), "f"(v[t].y), "f"(v[t].z), "f"(v[t].w) : "memory");
    }
    if (lane < 4) {
        asm volatile("red.global.add.f32 [%0], %1;"
                     :: "l"(g_cnt + dst[lane]), "f"(1.0f) : "memory");
    }
}

// ---------------- launch ----------------
extern "C" void kernel_launch(void* const* d_in, const int* in_sizes, int n_in,
                              void* d_out, int out_size) {
    const float* node_repr = (const float*)d_in[0];
    const int*   edges     = (const int*)d_in[1];
    const float* edge_w    = (const float*)d_in[2];

    const float* p0g = (const float*)d_in[3];  const float* p0b = (const float*)d_in[4];
    const float* p0m = (const float*)d_in[5];  const float* p0v = (const float*)d_in[6];
    const float* p0W = (const float*)d_in[7];  const float* p0bias = (const float*)d_in[8];
    const float* p1g = (const float*)d_in[9];  const float* p1b = (const float*)d_in[10];
    const float* p1m = (const float*)d_in[11]; const float* p1v = (const float*)d_in[12];
    const float* p1W = (const float*)d_in[13]; const float* p1bias = (const float*)d_in[14];
    const float* u0g = (const float*)d_in[15]; const float* u0b = (const float*)d_in[16];
    const float* u0m = (const float*)d_in[17]; const float* u0v = (const float*)d_in[18];
    const float* u0W = (const float*)d_in[19]; const float* u0bias = (const float*)d_in[20];
    const float* u1g = (const float*)d_in[21]; const float* u1b = (const float*)d_in[22];
    const float* u1m = (const float*)d_in[23]; const float* u1v = (const float*)d_in[24];
    const float* u1W = (const float*)d_in[25]; const float* u1bias = (const float*)d_in[26];

    float *pWp0, *pbp0, *pWp1, *pbp1, *pWu0, *pbu0, *pWu1, *pbu1, *pBufA, *pPrep;
    cudaGetSymbolAddress((void**)&pWp0, g_Wp0);
    cudaGetSymbolAddress((void**)&pbp0, g_bp0);
    cudaGetSymbolAddress((void**)&pWp1, g_Wp1);
    cudaGetSymbolAddress((void**)&pbp1, g_bp1);
    cudaGetSymbolAddress((void**)&pWu0, g_Wu0);
    cudaGetSymbolAddress((void**)&pbu0, g_bu0);
    cudaGetSymbolAddress((void**)&pWu1, g_Wu1);
    cudaGetSymbolAddress((void**)&pbu1, g_bu1);
    cudaGetSymbolAddress((void**)&pBufA, g_bufA);
    cudaGetSymbolAddress((void**)&pPrep, g_prep);

    const int smemB = (128 * 128 + 64 * 132) * 4;  // 99328 B
    cudaFuncSetAttribute(gemm_f2<1, false>, cudaFuncAttributeMaxDynamicSharedMemorySize, smemB);
    cudaFuncSetAttribute(gemm_f2<2, true>,  cudaFuncAttributeMaxDynamicSharedMemorySize, smemB);

    // 1) fold BN into weights/biases
    fold_w_all<<<320, 256>>>(p0g, p0v, p0W, pWp0,
                             p1g, p1v, p1W, pWp1,
                             u0g, u0v, u0W, pWu0,
                             u1g, u1v, u1W, pWu1);
    fold_b_all<<<4, 128>>>(p0g, p0b, p0m, p0v, p0W, p0bias, pbp0,
                           p1g, p1b, p1m, p1v, p1W, p1bias, pbp1,
                           u0g, u0b, u0m, u0v, u0W, u0bias, pbu0,
                           u1g, u1b, u1m, u1v, u1W, u1bias, pbu1);

    // 2) zero aggregation buffers
    zero_kernel<<<(NN * 128 / 4 + 255) / 256, 256>>>();

    const int gblocks = (NN + 63) / 64;  // 782
    // 3) prepare FFN applied once per NODE (16x algebraic reduction vs per-edge)
    gemm_f2<1, false><<<gblocks, 128, smemB>>>(node_repr, pWp0, pbp0, pBufA, NN);
    gemm_f2<1, false><<<gblocks, 128, smemB>>>(pBufA, pWp1, pbp1, pPrep, NN);

    // 4) scatter-aggregate along edges (4 edges per warp)
    scatter_kernel<<<EE / 32, 256>>>(edges, edge_w);

    // 5) update FFN: concat(node_repr, agg_mean) -> H, then H -> H (writes d_out)
    gemm_f2<2, true><<<gblocks, 128, smemB>>>(node_repr, pWu0, pbu0, pBufA, NN);
    gemm_f2<1, false><<<gblocks, 128, smemB>>>(pBufA, pWu1, pbu1, (float*)d_out, NN);
}

// round 5
// speedup vs baseline: 1.6610x; 1.0055x over previous
#include <cuda_runtime.h>
#include <math.h>

#define NN 50000
#define EE 800000
#define BN_EPS 1e-3f

typedef unsigned long long ull;

// ---------------- device scratch (no allocation allowed) ----------------
__device__ float g_Wp0[128 * 128];
__device__ float g_bp0[128];
__device__ float g_Wp1[128 * 128];
__device__ float g_bp1[128];
__device__ float g_Wu0[256 * 128];
__device__ float g_bu0[128];
__device__ float g_Wu1[128 * 128];
__device__ float g_bu1[128];

__device__ float g_bufA[NN * 128];   // intermediate activations
__device__ float g_prep[NN * 128];   // prep FFN output (per-node messages)
__device__ float g_agg[NN * 128];    // aggregated sums
__device__ float g_cnt[NN];          // per-node edge counts

// ---------------- helpers ----------------
__device__ __forceinline__ ull ffma2(ull a, ull b, ull c) {
    ull d;
    asm("fma.rn.f32x2 %0, %1, %2, %3;" : "=l"(d) : "l"(a), "l"(b), "l"(c));
    return d;
}
__device__ __forceinline__ ull pack2(float x) {
    ull r;
    asm("mov.b64 %0, {%1, %2};" : "=l"(r) : "f"(x), "f"(x));
    return r;
}
__device__ __forceinline__ void unpack2(ull v, float& lo, float& hi) {
    asm("mov.b64 {%0, %1}, %2;" : "=f"(lo), "=f"(hi) : "l"(v));
}
__device__ __forceinline__ float gelu_f(float x) {
    return 0.5f * x * (1.0f + erff(x * 0.70710678118654752f));
}

// ---------------- fused BN-fold kernels (2 launches total) ----------------
__global__ void fold_w_all(
    const float* __restrict__ g0, const float* __restrict__ v0, const float* __restrict__ W0, float* __restrict__ o0,
    const float* __restrict__ g1, const float* __restrict__ v1, const float* __restrict__ W1, float* __restrict__ o1,
    const float* __restrict__ g2, const float* __restrict__ v2, const float* __restrict__ W2, float* __restrict__ o2,
    const float* __restrict__ g3, const float* __restrict__ v3, const float* __restrict__ W3, float* __restrict__ o3) {
    int idx = blockIdx.x * 256 + threadIdx.x;
    const float *g, *v, *W;
    float* o;
    int base;
    if (idx < 16384)      { g = g0; v = v0; W = W0; o = o0; base = 0; }
    else if (idx < 32768) { g = g1; v = v1; W = W1; o = o1; base = 16384; }
    else if (idx < 65536) { g = g2; v = v2; W = W2; o = o2; base = 32768; }
    else                  { g = g3; v = v3; W = W3; o = o3; base = 65536; if (idx >= 81920) return; }
    int i = idx - base;
    int r = i >> 7;
    o[i] = W[i] * (g[r] * rsqrtf(v[r] + BN_EPS));
}

__global__ void fold_b_all(
    const float* __restrict__ g0, const float* __restrict__ b0, const float* __restrict__ m0, const float* __restrict__ v0, const float* __restrict__ W0, const float* __restrict__ s0, float* __restrict__ o0,
    const float* __restrict__ g1, const float* __restrict__ b1, const float* __restrict__ m1, const float* __restrict__ v1, const float* __restrict__ W1, const float* __restrict__ s1, float* __restrict__ o1,
    const float* __restrict__ g2, const float* __restrict__ b2, const float* __restrict__ m2, const float* __restrict__ v2, const float* __restrict__ W2, const float* __restrict__ s2, float* __restrict__ o2,
    const float* __restrict__ g3, const float* __restrict__ b3, const float* __restrict__ m3, const float* __restrict__ v3, const float* __restrict__ W3, const float* __restrict__ s3, float* __restrict__ o3) {
    int l = blockIdx.x;
    const float *g, *b, *m, *v, *W, *s;
    float* o;
    int K;
    switch (l) {
        case 0:  g = g0; b = b0; m = m0; v = v0; W = W0; s = s0; o = o0; K = 128; break;
        case 1:  g = g1; b = b1; m = m1; v = v1; W = W1; s = s1; o = o1; K = 128; break;
        case 2:  g = g2; b = b2; m = m2; v = v2; W = W2; s = s2; o = o2; K = 256; break;
        default: g = g3; b = b3; m = m3; v = v3; W = W3; s = s3; o = o3; K = 128; break;
    }
    int j = threadIdx.x;
    float acc0 = s[j], acc1 = 0.f;
    #pragma unroll 8
    for (int i = 0; i < K; i += 2) {
        float sc0 = g[i] * rsqrtf(v[i] + BN_EPS);
        float sc1 = g[i + 1] * rsqrtf(v[i + 1] + BN_EPS);
        acc0 = fmaf(b[i] - m[i] * sc0, W[i * 128 + j], acc0);
        acc1 = fmaf(b[i + 1] - m[i + 1] * sc1, W[(i + 1) * 128 + j], acc1);
    }
    o[j] = acc0 + acc1;
}

// ---------------- zero agg + cnt ----------------
__global__ void zero_kernel() {
    int i = blockIdx.x * 256 + threadIdx.x;
    float4 z = make_float4(0.f, 0.f, 0.f, 0.f);
    if (i < NN * 128 / 4) reinterpret_cast<float4*>(g_agg)[i] = z;
    if (i < NN / 4)       reinterpret_cast<float4*>(g_cnt)[i] = z;
}

// ---------------- GEMM + bias + gelu with packed f32x2 FMA ----------------
// Y[nrows,128] = gelu(X[nrows, CHUNKS*128] @ W' + b')
// 256 threads, block tile 64 rows x 128 cols, thread tile 4 rows x 8 cols.
// 2 blocks/SM -> 16 warps/SM = 4 warps/SMSP for latency hiding.
// c0 = (wid&3)*32 + (lane&3)*8 ; rbase = (wid>>2)*32 + (lane>>2); rows rbase+8i.
//   W LDS.128: 4 distinct contiguous 16B lines -> 1 wavefront (broadcast over lane>>2).
//   x LDS.128: 8 rows at 528B stride -> bank-distinct (broadcast over lane&3).
template <int CHUNKS, bool CONCAT>
__global__ void __launch_bounds__(256, 2)
gemm_f2(const float* __restrict__ X0, const float* __restrict__ W,
        const float* __restrict__ B, float* __restrict__ Y, int nrows) {
    constexpr int LDX = 132;             // 528B row stride in xs
    extern __shared__ float sm[];
    float* ws = sm;                      // 128*128 floats
    float* xs = sm + 128 * 128;          // 64*LDX floats

    const int tid = threadIdx.x;
    const int lane = tid & 31;
    const int wid = tid >> 5;
    const int c0 = (wid & 3) * 32 + (lane & 3) * 8;
    const int rbase = (wid >> 2) * 32 + (lane >> 2);
    const int row0 = blockIdx.x * 64;

    ull acc[4][4];
    #pragma unroll
    for (int i = 0; i < 4; i++)
        #pragma unroll
        for (int j = 0; j < 4; j++) acc[i][j] = 0ull;

    for (int cc = 0; cc < CHUNKS; cc++) {
        if (cc) __syncthreads();
        // stage W chunk (k rows cc*128 .. +127), row-major [k][128]
        {
            const float4* Wg = reinterpret_cast<const float4*>(W + cc * 128 * 128);
            float4* Ws4 = reinterpret_cast<float4*>(ws);
            #pragma unroll
            for (int i = tid; i < 128 * 32; i += 256) Ws4[i] = Wg[i];
        }
        // stage X chunk
        {
            const float* Xc = (CONCAT && cc == 1) ? g_agg : X0;
            #pragma unroll
            for (int idx = tid; idx < 64 * 32; idx += 256) {
                int r = idx >> 5, k4 = idx & 31;
                int row = row0 + r;
                float4 v = make_float4(0.f, 0.f, 0.f, 0.f);
                if (row < nrows) {
                    v = reinterpret_cast<const float4*>(Xc + (size_t)row * 128)[k4];
                    if (CONCAT && cc == 1) {
                        float cn = g_cnt[row];
                        float f = (cn > 0.f) ? (1.0f / cn) : 0.f;
                        v.x *= f; v.y *= f; v.z *= f; v.w *= f;
                    }
                }
                *reinterpret_cast<float4*>(xs + r * LDX + k4 * 4) = v;
            }
        }
        __syncthreads();

        float4 xa[4], xb[4];
        #pragma unroll
        for (int i = 0; i < 4; i++)
            xa[i] = *reinterpret_cast<const float4*>(xs + (rbase + 8 * i) * LDX);

        #pragma unroll 1
        for (int kg = 0; kg < 32; kg += 2) {
            // prefetch group kg+1 into xb, compute group kg from xa
            #pragma unroll
            for (int i = 0; i < 4; i++)
                xb[i] = *reinterpret_cast<const float4*>(xs + (rbase + 8 * i) * LDX + kg * 4 + 4);
            #pragma unroll
            for (int kk = 0; kk < 4; kk++) {
                int k = kg * 4 + kk;
                ulonglong2 wa = *reinterpret_cast<const ulonglong2*>(ws + k * 128 + c0);
                ulonglong2 wb = *reinterpret_cast<const ulonglong2*>(ws + k * 128 + c0 + 4);
                #pragma unroll
                for (int i = 0; i < 4; i++) {
                    const float* xp = reinterpret_cast<const float*>(&xa[i]);
                    ull xd = pack2(xp[kk]);
                    acc[i][0] = ffma2(xd, wa.x, acc[i][0]);
                    acc[i][1] = ffma2(xd, wa.y, acc[i][1]);
                    acc[i][2] = ffma2(xd, wb.x, acc[i][2]);
                    acc[i][3] = ffma2(xd, wb.y, acc[i][3]);
                }
            }
            // prefetch group kg+2 into xa (if any), compute group kg+1 from xb
            if (kg < 30) {
                #pragma unroll
                for (int i = 0; i < 4; i++)
                    xa[i] = *reinterpret_cast<const float4*>(xs + (rbase + 8 * i) * LDX + kg * 4 + 8);
            }
            #pragma unroll
            for (int kk = 0; kk < 4; kk++) {
                int k = kg * 4 + 4 + kk;
                ulonglong2 wa = *reinterpret_cast<const ulonglong2*>(ws + k * 128 + c0);
                ulonglong2 wb = *reinterpret_cast<const ulonglong2*>(ws + k * 128 + c0 + 4);
                #pragma unroll
                for (int i = 0; i < 4; i++) {
                    const float* xp = reinterpret_cast<const float*>(&xb[i]);
                    ull xd = pack2(xp[kk]);
                    acc[i][0] = ffma2(xd, wa.x, acc[i][0]);
                    acc[i][1] = ffma2(xd, wa.y, acc[i][1]);
                    acc[i][2] = ffma2(xd, wb.x, acc[i][2]);
                    acc[i][3] = ffma2(xd, wb.y, acc[i][3]);
                }
            }
        }
    }

    // epilogue: bias + gelu + store (rows rbase + 8*i)
    float4 bA = *reinterpret_cast<const float4*>(B + c0);
    float4 bB = *reinterpret_cast<const float4*>(B + c0 + 4);
    float bb[8] = {bA.x, bA.y, bA.z, bA.w, bB.x, bB.y, bB.z, bB.w};
    #pragma unroll
    for (int i = 0; i < 4; i++) {
        int row = row0 + rbase + 8 * i;
        if (row < nrows) {
            float o[8];
            #pragma unroll
            for (int j = 0; j < 4; j++) {
                float lo, hi;
                unpack2(acc[i][j], lo, hi);
                o[2 * j]     = gelu_f(lo + bb[2 * j]);
                o[2 * j + 1] = gelu_f(hi + bb[2 * j + 1]);
            }
            *reinterpret_cast<float4*>(Y + (size_t)row * 128 + c0) =
                make_float4(o[0], o[1], o[2], o[3]);
            *reinterpret_cast<float4*>(Y + (size_t)row * 128 + c0 + 4) =
                make_float4(o[4], o[5], o[6], o[7]);
        }
    }
}

// ---------------- edge scatter: 4 edges per warp, loads batched for MLP ----------------
__global__ void __launch_bounds__(256)
scatter_kernel(const int* __restrict__ edges, const float* __restrict__ ew) {
    int warp = blockIdx.x * 8 + (threadIdx.x >> 5);
    int lane = threadIdx.x & 31;
    int e0 = warp * 4;

    int dst[4], src[4];
    float w[4];
    #pragma unroll
    for (int t = 0; t < 4; t++) {
        dst[t] = __ldg(edges + e0 + t);
        src[t] = __ldg(edges + EE + e0 + t);
        w[t]   = __ldg(ew + e0 + t);
    }
    float4 v[4];
    #pragma unroll
    for (int t = 0; t < 4; t++)
        v[t] = __ldg(reinterpret_cast<const float4*>(g_prep + (size_t)src[t] * 128) + lane);
    #pragma unroll
    for (int t = 0; t < 4; t++) {
        v[t].x *= w[t]; v[t].y *= w[t]; v[t].z *= w[t]; v[t].w *= w[t];
        float* dp = g_agg + (size_t)dst[t] * 128 + lane * 4;
        asm volatile("red.global.add.v4.f32 [%0], {%1, %2, %3, %4};"
                     :: "l"(dp), "f"(v[t].x), "f"(v[t].y), "f"(v[t].z), "f"(v[t].w) : "memory");
    }
    if (lane < 4) {
        asm volatile("red.global.add.f32 [%0], %1;"
                     :: "l"(g_cnt + dst[lane]), "f"(1.0f) : "memory");
    }
}

// ---------------- launch ----------------
extern "C" void kernel_launch(void* const* d_in, const int* in_sizes, int n_in,
                              void* d_out, int out_size) {
    const float* node_repr = (const float*)d_in[0];
    const int*   edges     = (const int*)d_in[1];
    const float* edge_w    = (const float*)d_in[2];

    const float* p0g = (const float*)d_in[3];  const float* p0b = (const float*)d_in[4];
    const float* p0m = (const float*)d_in[5];  const float* p0v = (const float*)d_in[6];
    const float* p0W = (const float*)d_in[7];  const float* p0bias = (const float*)d_in[8];
    const float* p1g = (const float*)d_in[9];  const float* p1b = (const float*)d_in[10];
    const float* p1m = (const float*)d_in[11]; const float* p1v = (const float*)d_in[12];
    const float* p1W = (const float*)d_in[13]; const float* p1bias = (const float*)d_in[14];
    const float* u0g = (const float*)d_in[15]; const float* u0b = (const float*)d_in[16];
    const float* u0m = (const float*)d_in[17]; const float* u0v = (const float*)d_in[18];
    const float* u0W = (const float*)d_in[19]; const float* u0bias = (const float*)d_in[20];
    const float* u1g = (const float*)d_in[21]; const float* u1b = (const float*)d_in[22];
    const float* u1m = (const float*)d_in[23]; const float* u1v = (const float*)d_in[24];
    const float* u1W = (const float*)d_in[25]; const float* u1bias = (const float*)d_in[26];

    float *pWp0, *pbp0, *pWp1, *pbp1, *pWu0, *pbu0, *pWu1, *pbu1, *pBufA, *pPrep;
    cudaGetSymbolAddress((void**)&pWp0, g_Wp0);
    cudaGetSymbolAddress((void**)&pbp0, g_bp0);
    cudaGetSymbolAddress((void**)&pWp1, g_Wp1);
    cudaGetSymbolAddress((void**)&pbp1, g_bp1);
    cudaGetSymbolAddress((void**)&pWu0, g_Wu0);
    cudaGetSymbolAddress((void**)&pbu0, g_bu0);
    cudaGetSymbolAddress((void**)&pWu1, g_Wu1);
    cudaGetSymbolAddress((void**)&pbu1, g_bu1);
    cudaGetSymbolAddress((void**)&pBufA, g_bufA);
    cudaGetSymbolAddress((void**)&pPrep, g_prep);

    const int smemB = (128 * 128 + 64 * 132) * 4;  // 99328 B
    cudaFuncSetAttribute(gemm_f2<1, false>, cudaFuncAttributeMaxDynamicSharedMemorySize, smemB);
    cudaFuncSetAttribute(gemm_f2<2, true>,  cudaFuncAttributeMaxDynamicSharedMemorySize, smemB);

    // 1) fold BN into weights/biases
    fold_w_all<<<320, 256>>>(p0g, p0v, p0W, pWp0,
                             p1g, p1v, p1W, pWp1,
                             u0g, u0v, u0W, pWu0,
                             u1g, u1v, u1W, pWu1);
    fold_b_all<<<4, 128>>>(p0g, p0b, p0m, p0v, p0W, p0bias, pbp0,
                           p1g, p1b, p1m, p1v, p1W, p1bias, pbp1,
                           u0g, u0b, u0m, u0v, u0W, u0bias, pbu0,
                           u1g, u1b, u1m, u1v, u1W, u1bias, pbu1);

    // 2) zero aggregation buffers
    zero_kernel<<<(NN * 128 / 4 + 255) / 256, 256>>>();

    const int gblocks = (NN + 63) / 64;  // 782
    // 3) prepare FFN applied once per NODE (16x algebraic reduction vs per-edge)
    gemm_f2<1, false><<<gblocks, 256, smemB>>>(node_repr, pWp0, pbp0, pBufA, NN);
    gemm_f2<1, false><<<gblocks, 256, smemB>>>(pBufA, pWp1, pbp1, pPrep, NN);

    // 4) scatter-aggregate along edges (4 edges per warp)
    scatter_kernel<<<EE / 32, 256>>>(edges, edge_w);

    // 5) update FFN: concat(node_repr, agg_mean) -> H, then H -> H (writes d_out)
    gemm_f2<2, true><<<gblocks, 256, smemB>>>(node_repr, pWu0, pbu0, pBufA, NN);
    gemm_f2<1, false><<<gblocks, 256, smemB>>>(pBufA, pWu1, pbu1, (float*)d_out, NN);
}